// round 3
// baseline (speedup 1.0000x reference)
#include <cuda_runtime.h>
#include <cstdint>

// ----------------------------------------------------------------------------
// Problem constants
//   B=4, S=2048 -> T=8192 tokens, HID=768, NH=12, HD=64, NC=8 candidates,
//   FF=3072 (4*HID)
// ----------------------------------------------------------------------------
#define T_TOK   8192
#define HID     768
#define NH      12
#define HD      64
#define NC      8
#define FF      3072
#define CAND_M  (T_TOK * NC)   // 65536
#define MASK_N  (T_TOK * NC)   // 65536

// ----------------------------------------------------------------------------
// Scratch (device globals -- no allocation allowed anywhere)
// ----------------------------------------------------------------------------
__device__ float g_Q  [(size_t)T_TOK * HID];    //  25 MB
__device__ float g_K  [(size_t)CAND_M * HID];   // 201 MB
__device__ float g_V  [(size_t)CAND_M * HID];   // 201 MB
__device__ float g_CTX[(size_t)T_TOK * HID];    //  25 MB
__device__ float g_H  [(size_t)T_TOK * FF];     // 100 MB
__device__ float g_Y  [(size_t)T_TOK * HID];    //  25 MB
__device__ unsigned char g_mask[MASK_N];        //  64 KB normalized bool

// ----------------------------------------------------------------------------
// Mask normalization: the reference mask is a jax bool array; the harness may
// deliver it as uint8(bool), int32, or float32. Detect deterministically from
// the byte pattern of the first 65536 bytes (safe to read for all 3 dtypes),
// then write a normalized uint8 array.
//   - any byte > 1            -> float32 (exponent bytes like 0x3F/0x80 appear)
//   - some byte at i%4!=0 ==1 -> uint8/bool (an int32 0/1 array has those == 0)
//   - else                    -> int32  (also covers the all-zero case, where
//                                the int32 interpretation yields all-false,
//                                which is correct for every dtype)
// ----------------------------------------------------------------------------
__global__ void mask_norm_kernel(const void* __restrict__ mp)
{
    __shared__ int s_nonbin;
    __shared__ int s_offnz;
    const unsigned char* b = (const unsigned char*)mp;
    if (threadIdx.x == 0) { s_nonbin = 0; s_offnz = 0; }
    __syncthreads();

    int local_nonbin = 0, local_offnz = 0;
    for (int i = threadIdx.x; i < MASK_N; i += blockDim.x) {
        unsigned char v = b[i];
        if (v > 1)                 local_nonbin = 1;
        if ((i & 3) != 0 && v != 0) local_offnz = 1;
    }
    if (local_nonbin) atomicOr(&s_nonbin, 1);
    if (local_offnz)  atomicOr(&s_offnz, 1);
    __syncthreads();

    const int nonbin = s_nonbin, offnz = s_offnz;
    if (nonbin) {
        const float* f = (const float*)mp;
        for (int i = threadIdx.x; i < MASK_N; i += blockDim.x)
            g_mask[i] = (f[i] != 0.0f) ? 1 : 0;
    } else if (offnz) {
        for (int i = threadIdx.x; i < MASK_N; i += blockDim.x)
            g_mask[i] = (b[i] != 0) ? 1 : 0;
    } else {
        const int* ip = (const int*)mp;
        for (int i = threadIdx.x; i < MASK_N; i += blockDim.x)
            g_mask[i] = (ip[i] != 0) ? 1 : 0;
    }
}

// ----------------------------------------------------------------------------
// GELU (exact, matches jax.nn.gelu approximate=False)
// ----------------------------------------------------------------------------
__device__ __forceinline__ float gelu_f(float x)
{
    return 0.5f * x * (1.0f + erff(x * 0.70710678118654752440f));
}

// ----------------------------------------------------------------------------
// SGEMM:  C[M,N] = A[M,K] @ B[N,K]^T + bias[N]   (both operands K-major)
// Tiling: 128x128 CTA tile, BK=16, 256 threads, 8x8 per-thread microtile.
// All M,N,K in this problem are multiples of 128/16 -> no edge handling.
// gelu_flag != 0 applies exact GELU in the epilogue.
// ----------------------------------------------------------------------------
#define BM 128
#define BN 128
#define BK 16

__global__ __launch_bounds__(256)
void sgemm_bias(const float* __restrict__ A, const float* __restrict__ B,
                const float* __restrict__ bias, float* __restrict__ C,
                int M, int N, int K, int gelu_flag)
{
    __shared__ __align__(16) float As[BK][BM];
    __shared__ __align__(16) float Bs[BK][BN];

    const int tid = threadIdx.x;
    const int bm  = blockIdx.y * BM;
    const int bn  = blockIdx.x * BN;
    const int tx  = tid & 15;         // 0..15 -> N
    const int ty  = tid >> 4;         // 0..15 -> M

    const float* Ap = A + (size_t)bm * K;
    const float* Bp = B + (size_t)bn * K;

    float acc[8][8];
#pragma unroll
    for (int i = 0; i < 8; i++)
#pragma unroll
        for (int j = 0; j < 8; j++) acc[i][j] = 0.0f;

    for (int k0 = 0; k0 < K; k0 += BK) {
        // Load 128x16 tiles of A and B (each thread: 2 float4 per matrix,
        // fully coalesced: 4 consecutive lanes cover one 64B row segment).
#pragma unroll
        for (int i = 0; i < 2; i++) {
            int id  = i * 256 + tid;        // 0..511
            int row = id >> 2;              // 0..127
            int c4  = (id & 3) * 4;         // 0,4,8,12
            float4 a = *(const float4*)(Ap + (size_t)row * K + k0 + c4);
            As[c4 + 0][row] = a.x;
            As[c4 + 1][row] = a.y;
            As[c4 + 2][row] = a.z;
            As[c4 + 3][row] = a.w;
            float4 b = *(const float4*)(Bp + (size_t)row * K + k0 + c4);
            Bs[c4 + 0][row] = b.x;
            Bs[c4 + 1][row] = b.y;
            Bs[c4 + 2][row] = b.z;
            Bs[c4 + 3][row] = b.w;
        }
        __syncthreads();

#pragma unroll
        for (int kk = 0; kk < BK; kk++) {
            float ra[8], rb[8];
            *(float4*)&ra[0] = *(const float4*)&As[kk][ty * 8];
            *(float4*)&ra[4] = *(const float4*)&As[kk][ty * 8 + 4];
            *(float4*)&rb[0] = *(const float4*)&Bs[kk][tx * 8];
            *(float4*)&rb[4] = *(const float4*)&Bs[kk][tx * 8 + 4];
#pragma unroll
            for (int i = 0; i < 8; i++)
#pragma unroll
                for (int j = 0; j < 8; j++)
                    acc[i][j] += ra[i] * rb[j];
        }
        __syncthreads();
    }

    // Epilogue: bias (+ optional GELU), vectorized stores.
#pragma unroll
    for (int i = 0; i < 8; i++) {
        const int m = bm + ty * 8 + i;
#pragma unroll
        for (int j = 0; j < 8; j += 4) {
            const int n = bn + tx * 8 + j;
            float4 r;
            r.x = acc[i][j + 0] + bias[n + 0];
            r.y = acc[i][j + 1] + bias[n + 1];
            r.z = acc[i][j + 2] + bias[n + 2];
            r.w = acc[i][j + 3] + bias[n + 3];
            if (gelu_flag) {
                r.x = gelu_f(r.x); r.y = gelu_f(r.y);
                r.z = gelu_f(r.z); r.w = gelu_f(r.w);
            }
            *(float4*)(C + (size_t)m * N + n) = r;
        }
    }
}

// ----------------------------------------------------------------------------
// Attention: one warp per (token, head). 8 candidates, HD=64 (2 floats/lane).
//   scores[n] = dot(q, k_n)/8 ; masked -> 1e-10 (pre-softmax, as in reference)
//   softmax over n (all 8 entries participate)
//   ctx = sum_n p_n * v_n ; zeroed if all 8 candidates masked
// ----------------------------------------------------------------------------
__global__ __launch_bounds__(256)
void attn_kernel(const float* __restrict__ Q, const float* __restrict__ Kb,
                 const float* __restrict__ Vb, float* __restrict__ CTX)
{
    const int w    = (blockIdx.x * blockDim.x + threadIdx.x) >> 5;
    const int lane = threadIdx.x & 31;
    if (w >= T_TOK * NH) return;
    const int t = w / NH;
    const int h = w % NH;

    const size_t qoff = (size_t)t * HID + h * HD + lane * 2;
    const float2 q = *(const float2*)(Q + qoff);

    float s[NC];
    unsigned allm = 1;
#pragma unroll
    for (int n = 0; n < NC; n++) {
        const float2 kv = *(const float2*)(Kb + ((size_t)t * NC + n) * HID + h * HD + lane * 2);
        float p = q.x * kv.x + q.y * kv.y;
#pragma unroll
        for (int o = 16; o > 0; o >>= 1)
            p += __shfl_xor_sync(0xffffffffu, p, o);
        const unsigned char mn = g_mask[t * NC + n];
        allm &= (mn != 0);
        s[n] = mn ? 1e-10f : p * 0.125f;   // 1/sqrt(64)
    }

    float mx = s[0];
#pragma unroll
    for (int n = 1; n < NC; n++) mx = fmaxf(mx, s[n]);
    float sum = 0.0f;
#pragma unroll
    for (int n = 0; n < NC; n++) { s[n] = expf(s[n] - mx); sum += s[n]; }
    const float inv = 1.0f / sum;

    float2 c = make_float2(0.0f, 0.0f);
#pragma unroll
    for (int n = 0; n < NC; n++) {
        const float2 vv = *(const float2*)(Vb + ((size_t)t * NC + n) * HID + h * HD + lane * 2);
        const float p = s[n] * inv;
        c.x += p * vv.x;
        c.y += p * vv.y;
    }
    if (allm) { c.x = 0.0f; c.y = 0.0f; }
    *(float2*)(CTX + qoff) = c;
}

// ----------------------------------------------------------------------------
// Residual + LayerNorm: out = LN(Y + X) * gamma + beta, eps=1e-12
// One block (256 threads) per token, 3 elements per thread.
// ----------------------------------------------------------------------------
__global__ __launch_bounds__(256)
void ln_kernel(const float* __restrict__ Y, const float* __restrict__ X,
               const float* __restrict__ gamma, const float* __restrict__ beta,
               float* __restrict__ O)
{
    const int t   = blockIdx.x;
    const int tid = threadIdx.x;
    const float* yp = Y + (size_t)t * HID;
    const float* xp = X + (size_t)t * HID;

    float v[3];
    float sum = 0.0f, sq = 0.0f;
#pragma unroll
    for (int i = 0; i < 3; i++) {
        const int idx = tid + i * 256;
        v[i] = yp[idx] + xp[idx];
        sum += v[i];
        sq  += v[i] * v[i];
    }

    const int lane = tid & 31, wid = tid >> 5;
#pragma unroll
    for (int o = 16; o > 0; o >>= 1) {
        sum += __shfl_xor_sync(0xffffffffu, sum, o);
        sq  += __shfl_xor_sync(0xffffffffu, sq,  o);
    }
    __shared__ float rs[8], rq[8];
    if (lane == 0) { rs[wid] = sum; rq[wid] = sq; }
    __syncthreads();
    sum = 0.0f; sq = 0.0f;
#pragma unroll
    for (int i = 0; i < 8; i++) { sum += rs[i]; sq += rq[i]; }

    const float mean = sum * (1.0f / HID);
    const float var  = sq * (1.0f / HID) - mean * mean;
    const float inv  = rsqrtf(var + 1e-12f);

    float* op = O + (size_t)t * HID;
#pragma unroll
    for (int i = 0; i < 3; i++) {
        const int idx = tid + i * 256;
        op[idx] = (v[i] - mean) * inv * gamma[idx] + beta[idx];
    }
}

// ----------------------------------------------------------------------------
// kernel_launch
// ----------------------------------------------------------------------------
extern "C" void kernel_launch(void* const* d_in, const int* in_sizes, int n_in,
                              void* d_out, int out_size)
{
    const float* X    = (const float*)d_in[0];   // layer_output  [8192,768]
    const float* Cand = (const float*)d_in[1];   // candidates    [65536,768]
    const void*  Mask = d_in[2];                 // mask          [65536] (dtype auto-detected)
    const float* Wq   = (const float*)d_in[3];
    const float* bq   = (const float*)d_in[4];
    const float* Wk   = (const float*)d_in[5];
    const float* bk   = (const float*)d_in[6];
    const float* Wv   = (const float*)d_in[7];
    const float* bv   = (const float*)d_in[8];
    const float* Wt   = (const float*)d_in[9];   // [3072,768]
    const float* bt   = (const float*)d_in[10];  // [3072]
    const float* Wc   = (const float*)d_in[11];  // [768,3072]
    const float* bc   = (const float*)d_in[12];
    const float* gam  = (const float*)d_in[13];
    const float* bet  = (const float*)d_in[14];
    float* out = (float*)d_out;

    void *pQ, *pK, *pV, *pC, *pH, *pY;
    cudaGetSymbolAddress(&pQ, g_Q);
    cudaGetSymbolAddress(&pK, g_K);
    cudaGetSymbolAddress(&pV, g_V);
    cudaGetSymbolAddress(&pC, g_CTX);
    cudaGetSymbolAddress(&pH, g_H);
    cudaGetSymbolAddress(&pY, g_Y);

    // 0. Normalize the candidate mask (dtype-robust).
    mask_norm_kernel<<<1, 1024>>>(Mask);

    // 1. Q = X @ Wq^T + bq
    {
        dim3 grid(HID / BN, T_TOK / BM);
        sgemm_bias<<<grid, 256>>>(X, Wq, bq, (float*)pQ, T_TOK, HID, HID, 0);
    }
    // 2/3. K,V = Cand @ {Wk,Wv}^T + {bk,bv}
    {
        dim3 grid(HID / BN, CAND_M / BM);
        sgemm_bias<<<grid, 256>>>(Cand, Wk, bk, (float*)pK, CAND_M, HID, HID, 0);
        sgemm_bias<<<grid, 256>>>(Cand, Wv, bv, (float*)pV, CAND_M, HID, HID, 0);
    }
    // 4. attention -> CTX
    attn_kernel<<<(T_TOK * NH) / 8, 256>>>((const float*)pQ, (const float*)pK,
                                           (const float*)pV, (float*)pC);
    // 5. H = gelu(CTX @ Wt^T + bt)
    {
        dim3 grid(FF / BN, T_TOK / BM);
        sgemm_bias<<<grid, 256>>>((const float*)pC, Wt, bt, (float*)pH, T_TOK, FF, HID, 1);
    }
    // 6. Y = H @ Wc^T + bc
    {
        dim3 grid(HID / BN, T_TOK / BM);
        sgemm_bias<<<grid, 256>>>((const float*)pH, Wc, bc, (float*)pY, T_TOK, HID, FF, 0);
    }
    // 7. out = LayerNorm(Y + X)
    ln_kernel<<<T_TOK, 256>>>((const float*)pY, X, gam, bet, out);
}

// round 7
// speedup vs baseline: 2.3023x; 2.3023x over previous
#include <cuda_runtime.h>
#include <cuda_bf16.h>
#include <cstdint>

// ----------------------------------------------------------------------------
// Problem constants: B=4, S=2048 -> T=8192 tokens, HID=768, NH=12, HD=64,
// NC=8 candidates, FF=3072
// ----------------------------------------------------------------------------
#define T_TOK   8192
#define HID     768
#define NH      12
#define HD      64
#define NC      8
#define FF      3072
#define CAND_M  (T_TOK * NC)   // 65536
#define MASK_N  (T_TOK * NC)   // 65536

typedef __nv_bfloat16  bf16;
typedef __nv_bfloat162 bf162;

// ----------------------------------------------------------------------------
// Scratch (device globals -- no allocation allowed anywhere)
// ----------------------------------------------------------------------------
__device__ float g_Q  [(size_t)T_TOK  * HID];   //  25 MB fp32
__device__ float g_K  [(size_t)CAND_M * HID];   // 201 MB fp32
__device__ float g_V  [(size_t)CAND_M * HID];   // 201 MB fp32
__device__ float g_Y  [(size_t)T_TOK  * HID];   //  25 MB fp32
__device__ unsigned char g_mask[MASK_N];

// bf16 hi/lo split buffers
__device__ bf16 g_Xhi [(size_t)T_TOK  * HID];
__device__ bf16 g_Xlo [(size_t)T_TOK  * HID];
__device__ bf16 g_Chi [(size_t)CAND_M * HID];
__device__ bf16 g_Clo [(size_t)CAND_M * HID];
__device__ bf16 g_Wqhi[(size_t)HID * HID];
__device__ bf16 g_Wqlo[(size_t)HID * HID];
__device__ bf16 g_Wkhi[(size_t)HID * HID];
__device__ bf16 g_Wklo[(size_t)HID * HID];
__device__ bf16 g_Wvhi[(size_t)HID * HID];
__device__ bf16 g_Wvlo[(size_t)HID * HID];
__device__ bf16 g_Wthi[(size_t)FF * HID];
__device__ bf16 g_Wtlo[(size_t)FF * HID];
__device__ bf16 g_Wchi[(size_t)HID * FF];
__device__ bf16 g_Wclo[(size_t)HID * FF];
__device__ bf16 g_CXhi[(size_t)T_TOK * HID];
__device__ bf16 g_CXlo[(size_t)T_TOK * HID];
__device__ bf16 g_Hhi [(size_t)T_TOK * FF];
__device__ bf16 g_Hlo [(size_t)T_TOK * FF];

// ----------------------------------------------------------------------------
// Helpers
// ----------------------------------------------------------------------------
__device__ __forceinline__ uint32_t smem_to_u32(const void* p) {
    uint32_t a;
    asm("{ .reg .u64 t; cvta.to.shared.u64 t, %1; cvt.u32.u64 %0, t; }"
        : "=r"(a) : "l"(p));
    return a;
}

#define CP_ASYNC16(dst_u32, src_ptr) \
    asm volatile("cp.async.cg.shared.global [%0], [%1], 16;" \
                 :: "r"(dst_u32), "l"(src_ptr) : "memory")
#define CP_COMMIT()  asm volatile("cp.async.commit_group;" ::: "memory")
#define CP_WAIT0()   asm volatile("cp.async.wait_group 0;" ::: "memory")

// m16n8k16 bf16 MMA with fp32 accumulate (baseline PTX, works at compute_103)
__device__ __forceinline__ void mma16816(float* c, const uint32_t* a, const uint32_t* b)
{
    asm volatile(
        "mma.sync.aligned.m16n8k16.row.col.f32.bf16.bf16.f32 "
        "{%0,%1,%2,%3}, {%4,%5,%6,%7}, {%8,%9}, {%0,%1,%2,%3};"
        : "+f"(c[0]), "+f"(c[1]), "+f"(c[2]), "+f"(c[3])
        : "r"(a[0]), "r"(a[1]), "r"(a[2]), "r"(a[3]), "r"(b[0]), "r"(b[1]));
}

__device__ __forceinline__ float gelu_f(float x)
{
    return 0.5f * x * (1.0f + erff(x * 0.70710678118654752440f));
}

// ----------------------------------------------------------------------------
// GEMM:  D[M,N] = (Ahi+Alo)[M,K] @ (Bhi+Blo)[N,K]^T + bias[N]
// 3-term bf16 split, fp32 accumulation via mma.sync.m16n8k16.
// CTA tile 128x128, K-chunk 32, 256 threads (8 warps, warp tile 64x32).
// Double-buffered smem, cp.async prefetch. Padded smem stride (40 bf16) is
// conflict-free for the mma fragment access pattern.
// Epilogue: fp32 out (outF) OR bf16 hi/lo split out; optional exact GELU.
// ----------------------------------------------------------------------------
#define SKP         40                      // smem row stride in bf16 (80 B)
#define MAT_BYTES   (128 * SKP * 2)         // 10240 B per matrix tile
#define STAGE_BYTES (4 * MAT_BYTES)         // Ahi,Alo,Bhi,Blo
#define GEMM_SMEM_TOTAL (2 * STAGE_BYTES)   // 81920 B

__global__ void __launch_bounds__(256)
gemm_bf16split(const bf16* __restrict__ Ahi, const bf16* __restrict__ Alo,
               const bf16* __restrict__ Bhi, const bf16* __restrict__ Blo,
               const float* __restrict__ bias,
               float* __restrict__ outF,
               bf16* __restrict__ outHi, bf16* __restrict__ outLo,
               int M, int N, int K, int gelu_flag)
{
    extern __shared__ __align__(16) char sm[];
    const uint32_t smem_u32 = smem_to_u32(sm);
    const int tid  = threadIdx.x;
    const int wid  = tid >> 5;
    const int lane = tid & 31;
    const int bm = blockIdx.y * 128;
    const int bn = blockIdx.x * 128;
    const int wm = (wid >> 2) * 64;     // warp M offset: 0 / 64
    const int wn = (wid & 3) * 32;      // warp N offset: 0/32/64/96

    // global->smem loader coords: 2 rows per thread per matrix tile
    const int lrow = tid >> 2;          // 0..63 (and +64)
    const int lseg = tid & 3;           // 16B segment within 64B row

    float acc[4][4][4];
#pragma unroll
    for (int i = 0; i < 4; i++)
#pragma unroll
        for (int j = 0; j < 4; j++)
#pragma unroll
            for (int r = 0; r < 4; r++) acc[i][j][r] = 0.0f;

    auto prefetch = [&](int k0, int s) {
        const uint32_t sb = smem_u32 + s * STAGE_BYTES;
#pragma unroll
        for (int h = 0; h < 2; h++) {
            const int r = lrow + h * 64;
            const uint32_t so = (uint32_t)(r * 80 + lseg * 16);
            const size_t ga = (size_t)(bm + r) * K + k0 + lseg * 8;
            const size_t gb = (size_t)(bn + r) * K + k0 + lseg * 8;
            CP_ASYNC16(sb + 0 * MAT_BYTES + so, Ahi + ga);
            CP_ASYNC16(sb + 1 * MAT_BYTES + so, Alo + ga);
            CP_ASYNC16(sb + 2 * MAT_BYTES + so, Bhi + gb);
            CP_ASYNC16(sb + 3 * MAT_BYTES + so, Blo + gb);
        }
    };

    const int nchunks = K >> 5;
    prefetch(0, 0);
    CP_COMMIT();

    // fragment lane offsets (bytes) within a matrix tile
    const int a_off = ((lane >> 2) * SKP + (lane & 3) * 2) * 2;  // + row*SKP*2 later
    // A frag regs: a0=(r,c) a1=(r+8,c) a2=(r,c+8) a3=(r+8,c+8); pairs are 32-bit
    // B frag regs: b0=(n,k) b1=(n,k+8)

    for (int c = 0; c < nchunks; c++) {
        const int s = c & 1;
        CP_WAIT0();
        __syncthreads();
        if (c + 1 < nchunks) prefetch((c + 1) << 5, s ^ 1);
        CP_COMMIT();

        const char* st   = sm + s * STAGE_BYTES;
        const char* mAhi = st;
        const char* mAlo = st + MAT_BYTES;
        const char* mBhi = st + 2 * MAT_BYTES;
        const char* mBlo = st + 3 * MAT_BYTES;

#pragma unroll
        for (int kk = 0; kk < 32; kk += 16) {
            uint32_t af[4][4], bh[4][2], bl[4][2];

            // term 1: Ahi x Bhi
#pragma unroll
            for (int mi = 0; mi < 4; mi++) {
                const char* p = mAhi + a_off + ((wm + mi * 16) * SKP + kk) * 2;
                af[mi][0] = *(const uint32_t*)(p);
                af[mi][1] = *(const uint32_t*)(p + 8 * SKP * 2);
                af[mi][2] = *(const uint32_t*)(p + 16);
                af[mi][3] = *(const uint32_t*)(p + 8 * SKP * 2 + 16);
            }
#pragma unroll
            for (int ni = 0; ni < 4; ni++) {
                const char* p = mBhi + a_off + ((wn + ni * 8) * SKP + kk) * 2;
                bh[ni][0] = *(const uint32_t*)(p);
                bh[ni][1] = *(const uint32_t*)(p + 16);
            }
#pragma unroll
            for (int mi = 0; mi < 4; mi++)
#pragma unroll
                for (int ni = 0; ni < 4; ni++)
                    mma16816(acc[mi][ni], af[mi], bh[ni]);

            // term 2: Ahi x Blo
#pragma unroll
            for (int ni = 0; ni < 4; ni++) {
                const char* p = mBlo + a_off + ((wn + ni * 8) * SKP + kk) * 2;
                bl[ni][0] = *(const uint32_t*)(p);
                bl[ni][1] = *(const uint32_t*)(p + 16);
            }
#pragma unroll
            for (int mi = 0; mi < 4; mi++)
#pragma unroll
                for (int ni = 0; ni < 4; ni++)
                    mma16816(acc[mi][ni], af[mi], bl[ni]);

            // term 3: Alo x Bhi (reload A frags from lo tile)
#pragma unroll
            for (int mi = 0; mi < 4; mi++) {
                const char* p = mAlo + a_off + ((wm + mi * 16) * SKP + kk) * 2;
                af[mi][0] = *(const uint32_t*)(p);
                af[mi][1] = *(const uint32_t*)(p + 8 * SKP * 2);
                af[mi][2] = *(const uint32_t*)(p + 16);
                af[mi][3] = *(const uint32_t*)(p + 8 * SKP * 2 + 16);
            }
#pragma unroll
            for (int mi = 0; mi < 4; mi++)
#pragma unroll
                for (int ni = 0; ni < 4; ni++)
                    mma16816(acc[mi][ni], af[mi], bh[ni]);
        }
        __syncthreads();
    }

    // ------------------------------------------------------------------ epilogue
#pragma unroll
    for (int mi = 0; mi < 4; mi++) {
        const int r0 = bm + wm + mi * 16 + (lane >> 2);
#pragma unroll
        for (int ni = 0; ni < 4; ni++) {
            const int c0 = bn + wn + ni * 8 + (lane & 3) * 2;
            const float b0 = bias[c0], b1 = bias[c0 + 1];
            float v0 = acc[mi][ni][0] + b0;
            float v1 = acc[mi][ni][1] + b1;
            float v2 = acc[mi][ni][2] + b0;
            float v3 = acc[mi][ni][3] + b1;
            if (gelu_flag) {
                v0 = gelu_f(v0); v1 = gelu_f(v1);
                v2 = gelu_f(v2); v3 = gelu_f(v3);
            }
            if (outF) {
                *(float2*)(outF + (size_t)r0 * N + c0)       = make_float2(v0, v1);
                *(float2*)(outF + (size_t)(r0 + 8) * N + c0) = make_float2(v2, v3);
            } else {
                const bf16 h0 = __float2bfloat16(v0);
                const bf16 h1 = __float2bfloat16(v1);
                const bf16 h2 = __float2bfloat16(v2);
                const bf16 h3 = __float2bfloat16(v3);
                bf162 hp0; hp0.x = h0; hp0.y = h1;
                bf162 hp1; hp1.x = h2; hp1.y = h3;
                bf162 lp0; lp0.x = __float2bfloat16(v0 - __bfloat162float(h0));
                lp0.y = __float2bfloat16(v1 - __bfloat162float(h1));
                bf162 lp1; lp1.x = __float2bfloat16(v2 - __bfloat162float(h2));
                lp1.y = __float2bfloat16(v3 - __bfloat162float(h3));
                *(bf162*)(outHi + (size_t)r0 * N + c0)       = hp0;
                *(bf162*)(outHi + (size_t)(r0 + 8) * N + c0) = hp1;
                *(bf162*)(outLo + (size_t)r0 * N + c0)       = lp0;
                *(bf162*)(outLo + (size_t)(r0 + 8) * N + c0) = lp1;
            }
        }
    }
}

// ----------------------------------------------------------------------------
// fp32 -> bf16 hi/lo split
// ----------------------------------------------------------------------------
__global__ __launch_bounds__(256)
void split_kernel(const float* __restrict__ in, bf16* __restrict__ hi,
                  bf16* __restrict__ lo, int n)
{
    const int i = (blockIdx.x * 256 + threadIdx.x) * 4;
    if (i >= n) return;
    const float4 v = *(const float4*)(in + i);
    const bf16 h0 = __float2bfloat16(v.x);
    const bf16 h1 = __float2bfloat16(v.y);
    const bf16 h2 = __float2bfloat16(v.z);
    const bf16 h3 = __float2bfloat16(v.w);
    const bf16 l0 = __float2bfloat16(v.x - __bfloat162float(h0));
    const bf16 l1 = __float2bfloat16(v.y - __bfloat162float(h1));
    const bf16 l2 = __float2bfloat16(v.z - __bfloat162float(h2));
    const bf16 l3 = __float2bfloat16(v.w - __bfloat162float(h3));
    bf162 hp0; hp0.x = h0; hp0.y = h1;
    bf162 hp1; hp1.x = h2; hp1.y = h3;
    bf162 lp0; lp0.x = l0; lp0.y = l1;
    bf162 lp1; lp1.x = l2; lp1.y = l3;
    uint2 hv, lv;
    hv.x = *(const uint32_t*)&hp0; hv.y = *(const uint32_t*)&hp1;
    lv.x = *(const uint32_t*)&lp0; lv.y = *(const uint32_t*)&lp1;
    *(uint2*)(hi + i) = hv;
    *(uint2*)(lo + i) = lv;
}

// ----------------------------------------------------------------------------
// Mask normalization (dtype-robust: bool/uint8, int32, or float32 -> uint8)
// ----------------------------------------------------------------------------
__global__ void mask_norm_kernel(const void* __restrict__ mp)
{
    __shared__ int s_nonbin;
    __shared__ int s_offnz;
    const unsigned char* b = (const unsigned char*)mp;
    if (threadIdx.x == 0) { s_nonbin = 0; s_offnz = 0; }
    __syncthreads();

    int local_nonbin = 0, local_offnz = 0;
    for (int i = threadIdx.x; i < MASK_N; i += blockDim.x) {
        unsigned char v = b[i];
        if (v > 1)                  local_nonbin = 1;
        if ((i & 3) != 0 && v != 0) local_offnz = 1;
    }
    if (local_nonbin) atomicOr(&s_nonbin, 1);
    if (local_offnz)  atomicOr(&s_offnz, 1);
    __syncthreads();

    const int nonbin = s_nonbin, offnz = s_offnz;
    if (nonbin) {
        const float* f = (const float*)mp;
        for (int i = threadIdx.x; i < MASK_N; i += blockDim.x)
            g_mask[i] = (f[i] != 0.0f) ? 1 : 0;
    } else if (offnz) {
        for (int i = threadIdx.x; i < MASK_N; i += blockDim.x)
            g_mask[i] = (b[i] != 0) ? 1 : 0;
    } else {
        const int* ip = (const int*)mp;
        for (int i = threadIdx.x; i < MASK_N; i += blockDim.x)
            g_mask[i] = (ip[i] != 0) ? 1 : 0;
    }
}

// ----------------------------------------------------------------------------
// Attention: one warp per (token, head). Writes CTX directly as bf16 hi/lo.
// ----------------------------------------------------------------------------
__global__ __launch_bounds__(256)
void attn_kernel(const float* __restrict__ Q, const float* __restrict__ Kb,
                 const float* __restrict__ Vb,
                 bf16* __restrict__ CXhi, bf16* __restrict__ CXlo)
{
    const int w    = (blockIdx.x * blockDim.x + threadIdx.x) >> 5;
    const int lane = threadIdx.x & 31;
    if (w >= T_TOK * NH) return;
    const int t = w / NH;
    const int h = w % NH;

    const size_t qoff = (size_t)t * HID + h * HD + lane * 2;
    const float2 q = *(const float2*)(Q + qoff);

    float s[NC];
    unsigned allm = 1;
#pragma unroll
    for (int n = 0; n < NC; n++) {
        const float2 kv = *(const float2*)(Kb + ((size_t)t * NC + n) * HID + h * HD + lane * 2);
        float p = q.x * kv.x + q.y * kv.y;
#pragma unroll
        for (int o = 16; o > 0; o >>= 1)
            p += __shfl_xor_sync(0xffffffffu, p, o);
        const unsigned char mn = g_mask[t * NC + n];
        allm &= (mn != 0);
        s[n] = mn ? 1e-10f : p * 0.125f;
    }

    float mx = s[0];
#pragma unroll
    for (int n = 1; n < NC; n++) mx = fmaxf(mx, s[n]);
    float sum = 0.0f;
#pragma unroll
    for (int n = 0; n < NC; n++) { s[n] = expf(s[n] - mx); sum += s[n]; }
    const float inv = 1.0f / sum;

    float2 c = make_float2(0.0f, 0.0f);
#pragma unroll
    for (int n = 0; n < NC; n++) {
        const float2 vv = *(const float2*)(Vb + ((size_t)t * NC + n) * HID + h * HD + lane * 2);
        const float p = s[n] * inv;
        c.x += p * vv.x;
        c.y += p * vv.y;
    }
    if (allm) { c.x = 0.0f; c.y = 0.0f; }

    const bf16 h0 = __float2bfloat16(c.x);
    const bf16 h1 = __float2bfloat16(c.y);
    const bf16 l0 = __float2bfloat16(c.x - __bfloat162float(h0));
    const bf16 l1 = __float2bfloat16(c.y - __bfloat162float(h1));
    bf162 hp; hp.x = h0; hp.y = h1;
    bf162 lp; lp.x = l0; lp.y = l1;
    *(bf162*)(CXhi + qoff) = hp;
    *(bf162*)(CXlo + qoff) = lp;
}

// ----------------------------------------------------------------------------
// Residual + LayerNorm
// ----------------------------------------------------------------------------
__global__ __launch_bounds__(256)
void ln_kernel(const float* __restrict__ Y, const float* __restrict__ X,
               const float* __restrict__ gamma, const float* __restrict__ beta,
               float* __restrict__ O)
{
    const int t   = blockIdx.x;
    const int tid = threadIdx.x;
    const float* yp = Y + (size_t)t * HID;
    const float* xp = X + (size_t)t * HID;

    float v[3];
    float sum = 0.0f, sq = 0.0f;
#pragma unroll
    for (int i = 0; i < 3; i++) {
        const int idx = tid + i * 256;
        v[i] = yp[idx] + xp[idx];
        sum += v[i];
        sq  += v[i] * v[i];
    }

    const int lane = tid & 31, wid = tid >> 5;
#pragma unroll
    for (int o = 16; o > 0; o >>= 1) {
        sum += __shfl_xor_sync(0xffffffffu, sum, o);
        sq  += __shfl_xor_sync(0xffffffffu, sq,  o);
    }
    __shared__ float rs[8], rq[8];
    if (lane == 0) { rs[wid] = sum; rq[wid] = sq; }
    __syncthreads();
    sum = 0.0f; sq = 0.0f;
#pragma unroll
    for (int i = 0; i < 8; i++) { sum += rs[i]; sq += rq[i]; }

    const float mean = sum * (1.0f / HID);
    const float var  = sq * (1.0f / HID) - mean * mean;
    const float inv  = rsqrtf(var + 1e-12f);

    float* op = O + (size_t)t * HID;
#pragma unroll
    for (int i = 0; i < 3; i++) {
        const int idx = tid + i * 256;
        op[idx] = (v[i] - mean) * inv * gamma[idx] + beta[idx];
    }
}

// ----------------------------------------------------------------------------
// kernel_launch
// ----------------------------------------------------------------------------
extern "C" void kernel_launch(void* const* d_in, const int* in_sizes, int n_in,
                              void* d_out, int out_size)
{
    const float* X    = (const float*)d_in[0];
    const float* Cand = (const float*)d_in[1];
    const void*  Mask = d_in[2];
    const float* Wq   = (const float*)d_in[3];
    const float* bq   = (const float*)d_in[4];
    const float* Wk   = (const float*)d_in[5];
    const float* bk   = (const float*)d_in[6];
    const float* Wv   = (const float*)d_in[7];
    const float* bv   = (const float*)d_in[8];
    const float* Wt   = (const float*)d_in[9];
    const float* bt   = (const float*)d_in[10];
    const float* Wc   = (const float*)d_in[11];
    const float* bc   = (const float*)d_in[12];
    const float* gam  = (const float*)d_in[13];
    const float* bet  = (const float*)d_in[14];
    float* out = (float*)d_out;

    void *pQ, *pK, *pV, *pY;
    void *pXhi, *pXlo, *pChi, *pClo;
    void *pWqhi, *pWqlo, *pWkhi, *pWklo, *pWvhi, *pWvlo;
    void *pWthi, *pWtlo, *pWchi, *pWclo;
    void *pCXhi, *pCXlo, *pHhi, *pHlo;
    cudaGetSymbolAddress(&pQ, g_Q);     cudaGetSymbolAddress(&pK, g_K);
    cudaGetSymbolAddress(&pV, g_V);     cudaGetSymbolAddress(&pY, g_Y);
    cudaGetSymbolAddress(&pXhi, g_Xhi); cudaGetSymbolAddress(&pXlo, g_Xlo);
    cudaGetSymbolAddress(&pChi, g_Chi); cudaGetSymbolAddress(&pClo, g_Clo);
    cudaGetSymbolAddress(&pWqhi, g_Wqhi); cudaGetSymbolAddress(&pWqlo, g_Wqlo);
    cudaGetSymbolAddress(&pWkhi, g_Wkhi); cudaGetSymbolAddress(&pWklo, g_Wklo);
    cudaGetSymbolAddress(&pWvhi, g_Wvhi); cudaGetSymbolAddress(&pWvlo, g_Wvlo);
    cudaGetSymbolAddress(&pWthi, g_Wthi); cudaGetSymbolAddress(&pWtlo, g_Wtlo);
    cudaGetSymbolAddress(&pWchi, g_Wchi); cudaGetSymbolAddress(&pWclo, g_Wclo);
    cudaGetSymbolAddress(&pCXhi, g_CXhi); cudaGetSymbolAddress(&pCXlo, g_CXlo);
    cudaGetSymbolAddress(&pHhi, g_Hhi);   cudaGetSymbolAddress(&pHlo, g_Hlo);

    cudaFuncSetAttribute(gemm_bf16split,
                         cudaFuncAttributeMaxDynamicSharedMemorySize,
                         GEMM_SMEM_TOTAL);

    // 0. mask normalization
    mask_norm_kernel<<<1, 1024>>>(Mask);

    // 1. fp32 -> bf16 hi/lo splits of all GEMM inputs
    split_kernel<<<(T_TOK * HID) / 1024, 256>>>(X,    (bf16*)pXhi, (bf16*)pXlo, T_TOK * HID);
    split_kernel<<<(CAND_M * HID) / 1024, 256>>>(Cand,(bf16*)pChi, (bf16*)pClo, CAND_M * HID);
    split_kernel<<<(HID * HID) / 1024, 256>>>(Wq,     (bf16*)pWqhi,(bf16*)pWqlo,HID * HID);
    split_kernel<<<(HID * HID) / 1024, 256>>>(Wk,     (bf16*)pWkhi,(bf16*)pWklo,HID * HID);
    split_kernel<<<(HID * HID) / 1024, 256>>>(Wv,     (bf16*)pWvhi,(bf16*)pWvlo,HID * HID);
    split_kernel<<<(FF * HID) / 1024, 256>>>(Wt,      (bf16*)pWthi,(bf16*)pWtlo,FF * HID);
    split_kernel<<<(HID * FF) / 1024, 256>>>(Wc,      (bf16*)pWchi,(bf16*)pWclo,HID * FF);

    // 2. Q = X @ Wq^T + bq   (fp32 out)
    {
        dim3 g(HID / 128, T_TOK / 128);
        gemm_bf16split<<<g, 256, GEMM_SMEM_TOTAL>>>(
            (const bf16*)pXhi, (const bf16*)pXlo,
            (const bf16*)pWqhi,(const bf16*)pWqlo, bq,
            (float*)pQ, nullptr, nullptr, T_TOK, HID, HID, 0);
    }
    // 3/4. K,V = Cand @ {Wk,Wv}^T + {bk,bv}   (fp32 out)
    {
        dim3 g(HID / 128, CAND_M / 128);
        gemm_bf16split<<<g, 256, GEMM_SMEM_TOTAL>>>(
            (const bf16*)pChi, (const bf16*)pClo,
            (const bf16*)pWkhi,(const bf16*)pWklo, bk,
            (float*)pK, nullptr, nullptr, CAND_M, HID, HID, 0);
        gemm_bf16split<<<g, 256, GEMM_SMEM_TOTAL>>>(
            (const bf16*)pChi, (const bf16*)pClo,
            (const bf16*)pWvhi,(const bf16*)pWvlo, bv,
            (float*)pV, nullptr, nullptr, CAND_M, HID, HID, 0);
    }
    // 5. attention -> CTX (bf16 hi/lo)
    attn_kernel<<<(T_TOK * NH) / 8, 256>>>((const float*)pQ, (const float*)pK,
                                           (const float*)pV,
                                           (bf16*)pCXhi, (bf16*)pCXlo);
    // 6. H = gelu(CTX @ Wt^T + bt)   (bf16 hi/lo out)
    {
        dim3 g(FF / 128, T_TOK / 128);
        gemm_bf16split<<<g, 256, GEMM_SMEM_TOTAL>>>(
            (const bf16*)pCXhi,(const bf16*)pCXlo,
            (const bf16*)pWthi,(const bf16*)pWtlo, bt,
            nullptr, (bf16*)pHhi, (bf16*)pHlo, T_TOK, FF, HID, 1);
    }
    // 7. Y = H @ Wc^T + bc   (fp32 out)
    {
        dim3 g(HID / 128, T_TOK / 128);
        gemm_bf16split<<<g, 256, GEMM_SMEM_TOTAL>>>(
            (const bf16*)pHhi, (const bf16*)pHlo,
            (const bf16*)pWchi,(const bf16*)pWclo, bc,
            (float*)pY, nullptr, nullptr, T_TOK, HID, FF, 0);
    }
    // 8. out = LayerNorm(Y + X)
    ln_kernel<<<T_TOK, 256>>>((const float*)pY, X, gam, bet, out);
}

// round 10
// speedup vs baseline: 2.5405x; 1.1035x over previous
#include <cuda_runtime.h>
#include <cuda_bf16.h>
#include <cstdint>

// ----------------------------------------------------------------------------
// Problem constants: B=4, S=2048 -> T=8192 tokens, HID=768, NH=12, HD=64,
// NC=8 candidates, FF=3072
// ----------------------------------------------------------------------------
#define T_TOK   8192
#define HID     768
#define NH      12
#define HD      64
#define NC      8
#define FF      3072
#define CAND_M  (T_TOK * NC)   // 65536
#define MASK_N  (T_TOK * NC)   // 65536

typedef __nv_bfloat16  bf16;
typedef __nv_bfloat162 bf162;

// ----------------------------------------------------------------------------
// Scratch (device globals -- no allocation allowed anywhere)
// ----------------------------------------------------------------------------
__device__ float g_Q  [(size_t)T_TOK  * HID];
__device__ float g_K  [(size_t)CAND_M * HID];
__device__ float g_V  [(size_t)CAND_M * HID];
__device__ float g_Y  [(size_t)T_TOK  * HID];
__device__ unsigned char g_mask[MASK_N];

__device__ bf16 g_Xhi [(size_t)T_TOK  * HID];
__device__ bf16 g_Xlo [(size_t)T_TOK  * HID];
__device__ bf16 g_Chi [(size_t)CAND_M * HID];
__device__ bf16 g_Clo [(size_t)CAND_M * HID];
__device__ bf16 g_Wqhi[(size_t)HID * HID];
__device__ bf16 g_Wqlo[(size_t)HID * HID];
__device__ bf16 g_Wkhi[(size_t)HID * HID];
__device__ bf16 g_Wklo[(size_t)HID * HID];
__device__ bf16 g_Wvhi[(size_t)HID * HID];
__device__ bf16 g_Wvlo[(size_t)HID * HID];
__device__ bf16 g_Wthi[(size_t)FF * HID];
__device__ bf16 g_Wtlo[(size_t)FF * HID];
__device__ bf16 g_Wchi[(size_t)HID * FF];
__device__ bf16 g_Wclo[(size_t)HID * FF];
__device__ bf16 g_CXhi[(size_t)T_TOK * HID];
__device__ bf16 g_CXlo[(size_t)T_TOK * HID];
__device__ bf16 g_Hhi [(size_t)T_TOK * FF];
__device__ bf16 g_Hlo [(size_t)T_TOK * FF];

// ----------------------------------------------------------------------------
// Helpers
// ----------------------------------------------------------------------------
__device__ __forceinline__ uint32_t smem_to_u32(const void* p) {
    uint32_t a;
    asm("{ .reg .u64 t; cvta.to.shared.u64 t, %1; cvt.u32.u64 %0, t; }"
        : "=r"(a) : "l"(p));
    return a;
}

#define CP_ASYNC16(dst_u32, src_ptr) \
    asm volatile("cp.async.cg.shared.global [%0], [%1], 16;" \
                 :: "r"(dst_u32), "l"(src_ptr) : "memory")
#define CP_COMMIT()  asm volatile("cp.async.commit_group;" ::: "memory")
#define CP_WAIT0()   asm volatile("cp.async.wait_group 0;" ::: "memory")

#define LDSM_X4(r0, r1, r2, r3, addr) \
    asm volatile("ldmatrix.sync.aligned.m8n8.x4.shared.b16 {%0,%1,%2,%3}, [%4];" \
                 : "=r"(r0), "=r"(r1), "=r"(r2), "=r"(r3) : "r"(addr))

// m16n8k16 bf16 MMA with fp32 accumulate (baseline PTX, works at compute_103)
__device__ __forceinline__ void mma16816(float* c, const uint32_t* a, const uint32_t* b)
{
    asm volatile(
        "mma.sync.aligned.m16n8k16.row.col.f32.bf16.bf16.f32 "
        "{%0,%1,%2,%3}, {%4,%5,%6,%7}, {%8,%9}, {%0,%1,%2,%3};"
        : "+f"(c[0]), "+f"(c[1]), "+f"(c[2]), "+f"(c[3])
        : "r"(a[0]), "r"(a[1]), "r"(a[2]), "r"(a[3]), "r"(b[0]), "r"(b[1]));
}

__device__ __forceinline__ float gelu_f(float x)
{
    return 0.5f * x * (1.0f + erff(x * 0.70710678118654752440f));
}

// ----------------------------------------------------------------------------
// GEMM:  D[M,N] = (Ahi+Alo)[M,K] @ (Bhi+Blo)[N,K]^T + bias[N]
// 3-term bf16 split, fp32 accumulation via mma.sync.m16n8k16.
// CTA tile 128x128, K-chunk 32, 512 threads (16 warps, warp tile 32x32).
// Fragments via ldmatrix.x4; double-buffered smem fed by cp.async.
//
// ldmatrix.x4 register<->matrix mapping (lane groups 0-7/8-15/16-23/24-31
// provide the addresses of matrices 0/1/2/3 in order):
//   A load at relA0: matrices = (r0-7,k0),(r8-15,k0),(r0-7,k8),(r8-15,k8)
//     -> exactly mma's {a0,a1,a2,a3}.
//   B load at relB0: matrices = (n0-7,k0),(n0-7,k8),(n8-15,k0),(n8-15,k8)
//     -> {b0,b1} of ni and {b0,b1} of ni+1, CONSECUTIVE. So each LDSM fills
//     bh[4g..4g+3] and the fragment pair for ni is &bh[ni*2]. (Round-8 bug:
//     results were interleaved into [0,1,4,5] with a mismatched index map,
//     swapping n8-15 <-> n16-23.)
// ----------------------------------------------------------------------------
#define SKP         40                      // smem row stride in bf16 (80 B)
#define MAT_BYTES   (128 * SKP * 2)         // 10240 B per matrix tile
#define STAGE_BYTES (4 * MAT_BYTES)         // Ahi,Alo,Bhi,Blo
#define GEMM_SMEM_TOTAL (2 * STAGE_BYTES)   // 81920 B

__global__ void __launch_bounds__(512)
gemm_bf16split(const bf16* __restrict__ Ahi, const bf16* __restrict__ Alo,
               const bf16* __restrict__ Bhi, const bf16* __restrict__ Blo,
               const float* __restrict__ bias,
               float* __restrict__ outF,
               bf16* __restrict__ outHi, bf16* __restrict__ outLo,
               int M, int N, int K, int gelu_flag)
{
    extern __shared__ __align__(16) char sm[];
    const uint32_t smem_u32 = smem_to_u32(sm);
    const int tid  = threadIdx.x;
    const int wid  = tid >> 5;
    const int lane = tid & 31;
    const int bm = blockIdx.y * 128;
    const int bn = blockIdx.x * 128;
    const int wm = (wid >> 2) * 32;     // warp M offset: 0/32/64/96
    const int wn = (wid & 3) * 32;      // warp N offset: 0/32/64/96

    // global->smem loader coords: one 16B segment per matrix per thread
    const int lrow = tid >> 2;          // 0..127
    const int lseg = tid & 3;           // 16B segment within 64B row

    // ldmatrix lane-relative byte offsets within a matrix tile (before kk*2):
    // A: lanes 0-7 -> rows 0-7 @k0 | 8-15 -> rows 8-15 @k0 |
    //    16-23 -> rows 0-7 @k8 | 24-31 -> rows 8-15 @k8
    const int aRow = (lane & 7) + ((lane >> 3) & 1) * 8;
    const int aCol = (lane >> 4) * 8;
    const uint32_t relA0 = (uint32_t)((wm +  0 + aRow) * SKP * 2 + aCol * 2);
    const uint32_t relA1 = (uint32_t)((wm + 16 + aRow) * SKP * 2 + aCol * 2);
    // B: lanes 0-7 -> n0-7 @k0 | 8-15 -> n0-7 @k8 | 16-23 -> n8-15 @k0 |
    //    24-31 -> n8-15 @k8
    const int bRow = (lane & 7) + (lane >> 4) * 8;
    const int bCol = ((lane >> 3) & 1) * 8;
    const uint32_t relB0 = (uint32_t)((wn +  0 + bRow) * SKP * 2 + bCol * 2);
    const uint32_t relB1 = (uint32_t)((wn + 16 + bRow) * SKP * 2 + bCol * 2);

    float acc[2][4][4];
#pragma unroll
    for (int i = 0; i < 2; i++)
#pragma unroll
        for (int j = 0; j < 4; j++)
#pragma unroll
            for (int r = 0; r < 4; r++) acc[i][j][r] = 0.0f;

    auto prefetch = [&](int k0, int s) {
        const uint32_t sb = smem_u32 + s * STAGE_BYTES;
        const uint32_t so = (uint32_t)(lrow * (SKP * 2) + lseg * 16);
        const size_t ga = (size_t)(bm + lrow) * K + k0 + lseg * 8;
        const size_t gb = (size_t)(bn + lrow) * K + k0 + lseg * 8;
        CP_ASYNC16(sb + 0 * MAT_BYTES + so, Ahi + ga);
        CP_ASYNC16(sb + 1 * MAT_BYTES + so, Alo + ga);
        CP_ASYNC16(sb + 2 * MAT_BYTES + so, Bhi + gb);
        CP_ASYNC16(sb + 3 * MAT_BYTES + so, Blo + gb);
    };

    const int nchunks = K >> 5;
    prefetch(0, 0);
    CP_COMMIT();

    for (int c = 0; c < nchunks; c++) {
        const int s = c & 1;
        CP_WAIT0();
        __syncthreads();
        if (c + 1 < nchunks) prefetch((c + 1) << 5, s ^ 1);
        CP_COMMIT();

        const uint32_t st = smem_u32 + s * STAGE_BYTES;

#pragma unroll
        for (int kk = 0; kk < 32; kk += 16) {
            const uint32_t kb = st + kk * 2;
            uint32_t ah[8], al[8], bh[8], bl[8];

            // A fragments: ah[mi*4 .. mi*4+3] = {a0,a1,a2,a3} for mi
            LDSM_X4(ah[0], ah[1], ah[2], ah[3], kb + relA0);
            LDSM_X4(ah[4], ah[5], ah[6], ah[7], kb + relA1);
            // B fragments: bh[ni*2], bh[ni*2+1] = {b0,b1} for ni (consecutive!)
            LDSM_X4(bh[0], bh[1], bh[2], bh[3], kb + 2 * MAT_BYTES + relB0);
            LDSM_X4(bh[4], bh[5], bh[6], bh[7], kb + 2 * MAT_BYTES + relB1);
            LDSM_X4(al[0], al[1], al[2], al[3], kb + MAT_BYTES + relA0);
            LDSM_X4(al[4], al[5], al[6], al[7], kb + MAT_BYTES + relA1);
            LDSM_X4(bl[0], bl[1], bl[2], bl[3], kb + 3 * MAT_BYTES + relB0);
            LDSM_X4(bl[4], bl[5], bl[6], bl[7], kb + 3 * MAT_BYTES + relB1);

#pragma unroll
            for (int mi = 0; mi < 2; mi++) {
#pragma unroll
                for (int ni = 0; ni < 4; ni++) {
                    mma16816(acc[mi][ni], &ah[mi * 4], &bh[ni * 2]);   // hi*hi
                    mma16816(acc[mi][ni], &ah[mi * 4], &bl[ni * 2]);   // hi*lo
                    mma16816(acc[mi][ni], &al[mi * 4], &bh[ni * 2]);   // lo*hi
                }
            }
        }
        __syncthreads();
    }

    // ------------------------------------------------------------------ epilogue
#pragma unroll
    for (int mi = 0; mi < 2; mi++) {
        const int r0 = bm + wm + mi * 16 + (lane >> 2);
#pragma unroll
        for (int ni = 0; ni < 4; ni++) {
            const int c0 = bn + wn + ni * 8 + (lane & 3) * 2;
            const float b0 = bias[c0], b1 = bias[c0 + 1];
            float v0 = acc[mi][ni][0] + b0;
            float v1 = acc[mi][ni][1] + b1;
            float v2 = acc[mi][ni][2] + b0;
            float v3 = acc[mi][ni][3] + b1;
            if (gelu_flag) {
                v0 = gelu_f(v0); v1 = gelu_f(v1);
                v2 = gelu_f(v2); v3 = gelu_f(v3);
            }
            if (outF) {
                *(float2*)(outF + (size_t)r0 * N + c0)       = make_float2(v0, v1);
                *(float2*)(outF + (size_t)(r0 + 8) * N + c0) = make_float2(v2, v3);
            } else {
                const bf16 h0 = __float2bfloat16(v0);
                const bf16 h1 = __float2bfloat16(v1);
                const bf16 h2 = __float2bfloat16(v2);
                const bf16 h3 = __float2bfloat16(v3);
                bf162 hp0; hp0.x = h0; hp0.y = h1;
                bf162 hp1; hp1.x = h2; hp1.y = h3;
                bf162 lp0; lp0.x = __float2bfloat16(v0 - __bfloat162float(h0));
                lp0.y = __float2bfloat16(v1 - __bfloat162float(h1));
                bf162 lp1; lp1.x = __float2bfloat16(v2 - __bfloat162float(h2));
                lp1.y = __float2bfloat16(v3 - __bfloat162float(h3));
                *(bf162*)(outHi + (size_t)r0 * N + c0)       = hp0;
                *(bf162*)(outHi + (size_t)(r0 + 8) * N + c0) = hp1;
                *(bf162*)(outLo + (size_t)r0 * N + c0)       = lp0;
                *(bf162*)(outLo + (size_t)(r0 + 8) * N + c0) = lp1;
            }
        }
    }
}

// ----------------------------------------------------------------------------
// fp32 -> bf16 hi/lo split
// ----------------------------------------------------------------------------
__global__ __launch_bounds__(256)
void split_kernel(const float* __restrict__ in, bf16* __restrict__ hi,
                  bf16* __restrict__ lo, int n)
{
    const int i = (blockIdx.x * 256 + threadIdx.x) * 4;
    if (i >= n) return;
    const float4 v = *(const float4*)(in + i);
    const bf16 h0 = __float2bfloat16(v.x);
    const bf16 h1 = __float2bfloat16(v.y);
    const bf16 h2 = __float2bfloat16(v.z);
    const bf16 h3 = __float2bfloat16(v.w);
    const bf16 l0 = __float2bfloat16(v.x - __bfloat162float(h0));
    const bf16 l1 = __float2bfloat16(v.y - __bfloat162float(h1));
    const bf16 l2 = __float2bfloat16(v.z - __bfloat162float(h2));
    const bf16 l3 = __float2bfloat16(v.w - __bfloat162float(h3));
    bf162 hp0; hp0.x = h0; hp0.y = h1;
    bf162 hp1; hp1.x = h2; hp1.y = h3;
    bf162 lp0; lp0.x = l0; lp0.y = l1;
    bf162 lp1; lp1.x = l2; lp1.y = l3;
    uint2 hv, lv;
    hv.x = *(const uint32_t*)&hp0; hv.y = *(const uint32_t*)&hp1;
    lv.x = *(const uint32_t*)&lp0; lv.y = *(const uint32_t*)&lp1;
    *(uint2*)(hi + i) = hv;
    *(uint2*)(lo + i) = lv;
}

// ----------------------------------------------------------------------------
// Mask normalization (dtype-robust: bool/uint8, int32, or float32 -> uint8)
// ----------------------------------------------------------------------------
__global__ void mask_norm_kernel(const void* __restrict__ mp)
{
    __shared__ int s_nonbin;
    __shared__ int s_offnz;
    const unsigned char* b = (const unsigned char*)mp;
    if (threadIdx.x == 0) { s_nonbin = 0; s_offnz = 0; }
    __syncthreads();

    int local_nonbin = 0, local_offnz = 0;
    for (int i = threadIdx.x; i < MASK_N; i += blockDim.x) {
        unsigned char v = b[i];
        if (v > 1)                  local_nonbin = 1;
        if ((i & 3) != 0 && v != 0) local_offnz = 1;
    }
    if (local_nonbin) atomicOr(&s_nonbin, 1);
    if (local_offnz)  atomicOr(&s_offnz, 1);
    __syncthreads();

    const int nonbin = s_nonbin, offnz = s_offnz;
    if (nonbin) {
        const float* f = (const float*)mp;
        for (int i = threadIdx.x; i < MASK_N; i += blockDim.x)
            g_mask[i] = (f[i] != 0.0f) ? 1 : 0;
    } else if (offnz) {
        for (int i = threadIdx.x; i < MASK_N; i += blockDim.x)
            g_mask[i] = (b[i] != 0) ? 1 : 0;
    } else {
        const int* ip = (const int*)mp;
        for (int i = threadIdx.x; i < MASK_N; i += blockDim.x)
            g_mask[i] = (ip[i] != 0) ? 1 : 0;
    }
}

// ----------------------------------------------------------------------------
// Attention: one warp per (token, head). Writes CTX directly as bf16 hi/lo.
// ----------------------------------------------------------------------------
__global__ __launch_bounds__(256)
void attn_kernel(const float* __restrict__ Q, const float* __restrict__ Kb,
                 const float* __restrict__ Vb,
                 bf16* __restrict__ CXhi, bf16* __restrict__ CXlo)
{
    const int w    = (blockIdx.x * blockDim.x + threadIdx.x) >> 5;
    const int lane = threadIdx.x & 31;
    if (w >= T_TOK * NH) return;
    const int t = w / NH;
    const int h = w % NH;

    const size_t qoff = (size_t)t * HID + h * HD + lane * 2;
    const float2 q = *(const float2*)(Q + qoff);

    float s[NC];
    unsigned allm = 1;
#pragma unroll
    for (int n = 0; n < NC; n++) {
        const float2 kv = *(const float2*)(Kb + ((size_t)t * NC + n) * HID + h * HD + lane * 2);
        float p = q.x * kv.x + q.y * kv.y;
#pragma unroll
        for (int o = 16; o > 0; o >>= 1)
            p += __shfl_xor_sync(0xffffffffu, p, o);
        const unsigned char mn = g_mask[t * NC + n];
        allm &= (mn != 0);
        s[n] = mn ? 1e-10f : p * 0.125f;
    }

    float mx = s[0];
#pragma unroll
    for (int n = 1; n < NC; n++) mx = fmaxf(mx, s[n]);
    float sum = 0.0f;
#pragma unroll
    for (int n = 0; n < NC; n++) { s[n] = expf(s[n] - mx); sum += s[n]; }
    const float inv = 1.0f / sum;

    float2 c = make_float2(0.0f, 0.0f);
#pragma unroll
    for (int n = 0; n < NC; n++) {
        const float2 vv = *(const float2*)(Vb + ((size_t)t * NC + n) * HID + h * HD + lane * 2);
        const float p = s[n] * inv;
        c.x += p * vv.x;
        c.y += p * vv.y;
    }
    if (allm) { c.x = 0.0f; c.y = 0.0f; }

    const bf16 h0 = __float2bfloat16(c.x);
    const bf16 h1 = __float2bfloat16(c.y);
    const bf16 l0 = __float2bfloat16(c.x - __bfloat162float(h0));
    const bf16 l1 = __float2bfloat16(c.y - __bfloat162float(h1));
    bf162 hp; hp.x = h0; hp.y = h1;
    bf162 lp; lp.x = l0; lp.y = l1;
    *(bf162*)(CXhi + qoff) = hp;
    *(bf162*)(CXlo + qoff) = lp;
}

// ----------------------------------------------------------------------------
// Residual + LayerNorm
// ----------------------------------------------------------------------------
__global__ __launch_bounds__(256)
void ln_kernel(const float* __restrict__ Y, const float* __restrict__ X,
               const float* __restrict__ gamma, const float* __restrict__ beta,
               float* __restrict__ O)
{
    const int t   = blockIdx.x;
    const int tid = threadIdx.x;
    const float* yp = Y + (size_t)t * HID;
    const float* xp = X + (size_t)t * HID;

    float v[3];
    float sum = 0.0f, sq = 0.0f;
#pragma unroll
    for (int i = 0; i < 3; i++) {
        const int idx = tid + i * 256;
        v[i] = yp[idx] + xp[idx];
        sum += v[i];
        sq  += v[i] * v[i];
    }

    const int lane = tid & 31, wid = tid >> 5;
#pragma unroll
    for (int o = 16; o > 0; o >>= 1) {
        sum += __shfl_xor_sync(0xffffffffu, sum, o);
        sq  += __shfl_xor_sync(0xffffffffu, sq,  o);
    }
    __shared__ float rs[8], rq[8];
    if (lane == 0) { rs[wid] = sum; rq[wid] = sq; }
    __syncthreads();
    sum = 0.0f; sq = 0.0f;
#pragma unroll
    for (int i = 0; i < 8; i++) { sum += rs[i]; sq += rq[i]; }

    const float mean = sum * (1.0f / HID);
    const float var  = sq * (1.0f / HID) - mean * mean;
    const float inv  = rsqrtf(var + 1e-12f);

    float* op = O + (size_t)t * HID;
#pragma unroll
    for (int i = 0; i < 3; i++) {
        const int idx = tid + i * 256;
        op[idx] = (v[i] - mean) * inv * gamma[idx] + beta[idx];
    }
}

// ----------------------------------------------------------------------------
// kernel_launch
// ----------------------------------------------------------------------------
extern "C" void kernel_launch(void* const* d_in, const int* in_sizes, int n_in,
                              void* d_out, int out_size)
{
    const float* X    = (const float*)d_in[0];
    const float* Cand = (const float*)d_in[1];
    const void*  Mask = d_in[2];
    const float* Wq   = (const float*)d_in[3];
    const float* bq   = (const float*)d_in[4];
    const float* Wk   = (const float*)d_in[5];
    const float* bk   = (const float*)d_in[6];
    const float* Wv   = (const float*)d_in[7];
    const float* bv   = (const float*)d_in[8];
    const float* Wt   = (const float*)d_in[9];
    const float* bt   = (const float*)d_in[10];
    const float* Wc   = (const float*)d_in[11];
    const float* bc   = (const float*)d_in[12];
    const float* gam  = (const float*)d_in[13];
    const float* bet  = (const float*)d_in[14];
    float* out = (float*)d_out;

    void *pQ, *pK, *pV, *pY;
    void *pXhi, *pXlo, *pChi, *pClo;
    void *pWqhi, *pWqlo, *pWkhi, *pWklo, *pWvhi, *pWvlo;
    void *pWthi, *pWtlo, *pWchi, *pWclo;
    void *pCXhi, *pCXlo, *pHhi, *pHlo;
    cudaGetSymbolAddress(&pQ, g_Q);     cudaGetSymbolAddress(&pK, g_K);
    cudaGetSymbolAddress(&pV, g_V);     cudaGetSymbolAddress(&pY, g_Y);
    cudaGetSymbolAddress(&pXhi, g_Xhi); cudaGetSymbolAddress(&pXlo, g_Xlo);
    cudaGetSymbolAddress(&pChi, g_Chi); cudaGetSymbolAddress(&pClo, g_Clo);
    cudaGetSymbolAddress(&pWqhi, g_Wqhi); cudaGetSymbolAddress(&pWqlo, g_Wqlo);
    cudaGetSymbolAddress(&pWkhi, g_Wkhi); cudaGetSymbolAddress(&pWklo, g_Wklo);
    cudaGetSymbolAddress(&pWvhi, g_Wvhi); cudaGetSymbolAddress(&pWvlo, g_Wvlo);
    cudaGetSymbolAddress(&pWthi, g_Wthi); cudaGetSymbolAddress(&pWtlo, g_Wtlo);
    cudaGetSymbolAddress(&pWchi, g_Wchi); cudaGetSymbolAddress(&pWclo, g_Wclo);
    cudaGetSymbolAddress(&pCXhi, g_CXhi); cudaGetSymbolAddress(&pCXlo, g_CXlo);
    cudaGetSymbolAddress(&pHhi, g_Hhi);   cudaGetSymbolAddress(&pHlo, g_Hlo);

    cudaFuncSetAttribute(gemm_bf16split,
                         cudaFuncAttributeMaxDynamicSharedMemorySize,
                         GEMM_SMEM_TOTAL);

    // 0. mask normalization
    mask_norm_kernel<<<1, 1024>>>(Mask);

    // 1. fp32 -> bf16 hi/lo splits of all GEMM inputs
    split_kernel<<<(T_TOK * HID) / 1024, 256>>>(X,    (bf16*)pXhi, (bf16*)pXlo, T_TOK * HID);
    split_kernel<<<(CAND_M * HID) / 1024, 256>>>(Cand,(bf16*)pChi, (bf16*)pClo, CAND_M * HID);
    split_kernel<<<(HID * HID) / 1024, 256>>>(Wq,     (bf16*)pWqhi,(bf16*)pWqlo,HID * HID);
    split_kernel<<<(HID * HID) / 1024, 256>>>(Wk,     (bf16*)pWkhi,(bf16*)pWklo,HID * HID);
    split_kernel<<<(HID * HID) / 1024, 256>>>(Wv,     (bf16*)pWvhi,(bf16*)pWvlo,HID * HID);
    split_kernel<<<(FF * HID) / 1024, 256>>>(Wt,      (bf16*)pWthi,(bf16*)pWtlo,FF * HID);
    split_kernel<<<(HID * FF) / 1024, 256>>>(Wc,      (bf16*)pWchi,(bf16*)pWclo,HID * FF);

    // 2. Q = X @ Wq^T + bq   (fp32 out)
    {
        dim3 g(HID / 128, T_TOK / 128);
        gemm_bf16split<<<g, 512, GEMM_SMEM_TOTAL>>>(
            (const bf16*)pXhi, (const bf16*)pXlo,
            (const bf16*)pWqhi,(const bf16*)pWqlo, bq,
            (float*)pQ, nullptr, nullptr, T_TOK, HID, HID, 0);
    }
    // 3/4. K,V = Cand @ {Wk,Wv}^T + {bk,bv}   (fp32 out)
    {
        dim3 g(HID / 128, CAND_M / 128);
        gemm_bf16split<<<g, 512, GEMM_SMEM_TOTAL>>>(
            (const bf16*)pChi, (const bf16*)pClo,
            (const bf16*)pWkhi,(const bf16*)pWklo, bk,
            (float*)pK, nullptr, nullptr, CAND_M, HID, HID, 0);
        gemm_bf16split<<<g, 512, GEMM_SMEM_TOTAL>>>(
            (const bf16*)pChi, (const bf16*)pClo,
            (const bf16*)pWvhi,(const bf16*)pWvlo, bv,
            (float*)pV, nullptr, nullptr, CAND_M, HID, HID, 0);
    }
    // 5. attention -> CTX (bf16 hi/lo)
    attn_kernel<<<(T_TOK * NH) / 8, 256>>>((const float*)pQ, (const float*)pK,
                                           (const float*)pV,
                                           (bf16*)pCXhi, (bf16*)pCXlo);
    // 6. H = gelu(CTX @ Wt^T + bt)   (bf16 hi/lo out)
    {
        dim3 g(FF / 128, T_TOK / 128);
        gemm_bf16split<<<g, 512, GEMM_SMEM_TOTAL>>>(
            (const bf16*)pCXhi,(const bf16*)pCXlo,
            (const bf16*)pWthi,(const bf16*)pWtlo, bt,
            nullptr, (bf16*)pHhi, (bf16*)pHlo, T_TOK, FF, HID, 1);
    }
    // 7. Y = H @ Wc^T + bc   (fp32 out)
    {
        dim3 g(HID / 128, T_TOK / 128);
        gemm_bf16split<<<g, 512, GEMM_SMEM_TOTAL>>>(
            (const bf16*)pHhi, (const bf16*)pHlo,
            (const bf16*)pWchi,(const bf16*)pWclo, bc,
            (float*)pY, nullptr, nullptr, T_TOK, HID, FF, 0);
    }
    // 8. out = LayerNorm(Y + X)
    ln_kernel<<<T_TOK, 256>>>((const float*)pY, X, gam, bet, out);
}

// round 11
// speedup vs baseline: 2.5432x; 1.0010x over previous
#include <cuda_runtime.h>
#include <cuda_bf16.h>
#include <cstdint>

// ----------------------------------------------------------------------------
// Problem constants: B=4, S=2048 -> T=8192 tokens, HID=768, NH=12, HD=64,
// NC=8 candidates, FF=3072
// ----------------------------------------------------------------------------
#define T_TOK   8192
#define HID     768
#define NH      12
#define HD      64
#define NC      8
#define FF      3072
#define CAND_M  (T_TOK * NC)   // 65536
#define MASK_N  (T_TOK * NC)   // 65536

typedef __nv_bfloat16  bf16;
typedef __nv_bfloat162 bf162;

// ----------------------------------------------------------------------------
// Scratch (device globals -- no allocation allowed anywhere)
// ----------------------------------------------------------------------------
__device__ float g_Q  [(size_t)T_TOK  * HID];
__device__ float g_K  [(size_t)CAND_M * HID];
__device__ float g_V  [(size_t)CAND_M * HID];
__device__ float g_Y  [(size_t)T_TOK  * HID];
__device__ unsigned char g_mask[MASK_N];

__device__ bf16 g_Xhi [(size_t)T_TOK  * HID];
__device__ bf16 g_Xlo [(size_t)T_TOK  * HID];
__device__ bf16 g_Chi [(size_t)CAND_M * HID];
__device__ bf16 g_Clo [(size_t)CAND_M * HID];
__device__ bf16 g_Wqhi[(size_t)HID * HID];
__device__ bf16 g_Wqlo[(size_t)HID * HID];
__device__ bf16 g_Wkhi[(size_t)HID * HID];
__device__ bf16 g_Wklo[(size_t)HID * HID];
__device__ bf16 g_Wvhi[(size_t)HID * HID];
__device__ bf16 g_Wvlo[(size_t)HID * HID];
__device__ bf16 g_Wthi[(size_t)FF * HID];
__device__ bf16 g_Wtlo[(size_t)FF * HID];
__device__ bf16 g_Wchi[(size_t)HID * FF];
__device__ bf16 g_Wclo[(size_t)HID * FF];
__device__ bf16 g_CXhi[(size_t)T_TOK * HID];
__device__ bf16 g_CXlo[(size_t)T_TOK * HID];
__device__ bf16 g_Hhi [(size_t)T_TOK * FF];
__device__ bf16 g_Hlo [(size_t)T_TOK * FF];

// ----------------------------------------------------------------------------
// Helpers
// ----------------------------------------------------------------------------
__device__ __forceinline__ uint32_t smem_to_u32(const void* p) {
    uint32_t a;
    asm("{ .reg .u64 t; cvta.to.shared.u64 t, %1; cvt.u32.u64 %0, t; }"
        : "=r"(a) : "l"(p));
    return a;
}

#define CP_ASYNC16(dst_u32, src_ptr) \
    asm volatile("cp.async.cg.shared.global [%0], [%1], 16;" \
                 :: "r"(dst_u32), "l"(src_ptr) : "memory")
#define CP_COMMIT()  asm volatile("cp.async.commit_group;" ::: "memory")
#define CP_WAIT0()   asm volatile("cp.async.wait_group 0;" ::: "memory")

#define LDSM_X4(r0, r1, r2, r3, addr) \
    asm volatile("ldmatrix.sync.aligned.m8n8.x4.shared.b16 {%0,%1,%2,%3}, [%4];" \
                 : "=r"(r0), "=r"(r1), "=r"(r2), "=r"(r3) : "r"(addr))

// m16n8k16 bf16 MMA with fp32 accumulate (baseline PTX, works at compute_103)
__device__ __forceinline__ void mma16816(float* c, const uint32_t* a, const uint32_t* b)
{
    asm volatile(
        "mma.sync.aligned.m16n8k16.row.col.f32.bf16.bf16.f32 "
        "{%0,%1,%2,%3}, {%4,%5,%6,%7}, {%8,%9}, {%0,%1,%2,%3};"
        : "+f"(c[0]), "+f"(c[1]), "+f"(c[2]), "+f"(c[3])
        : "r"(a[0]), "r"(a[1]), "r"(a[2]), "r"(a[3]), "r"(b[0]), "r"(b[1]));
}

__device__ __forceinline__ float gelu_f(float x)
{
    return 0.5f * x * (1.0f + erff(x * 0.70710678118654752440f));
}

// ----------------------------------------------------------------------------
// GEMM:  D[M,N] = (Ahi+Alo)[M,K] @ (Bhi+Blo)[N,K]^T + bias[N]
// 3-term bf16 split, fp32 accumulation via mma.sync.m16n8k16.
// CTA tile 128x128, K-chunk 32, 512 threads (16 warps, warp tile 32x32).
// Fragments via ldmatrix.x4; double-buffered smem fed by cp.async.
//
// MMA schedule: term-major (all 8 (mi,ni) MMAs of hi*hi, then hi*lo, then
// lo*hi) so consecutive MMAs never share an accumulator -> 8 independent
// MMAs between RAW reuses (Round-9 had 3 dependent MMAs back-to-back on the
// same acc, serializing the tensor pipe).
// ----------------------------------------------------------------------------
#define SKP         40                      // smem row stride in bf16 (80 B)
#define MAT_BYTES   (128 * SKP * 2)         // 10240 B per matrix tile
#define STAGE_BYTES (4 * MAT_BYTES)         // Ahi,Alo,Bhi,Blo
#define GEMM_SMEM_TOTAL (2 * STAGE_BYTES)   // 81920 B

__global__ void __launch_bounds__(512)
gemm_bf16split(const bf16* __restrict__ Ahi, const bf16* __restrict__ Alo,
               const bf16* __restrict__ Bhi, const bf16* __restrict__ Blo,
               const float* __restrict__ bias,
               float* __restrict__ outF,
               bf16* __restrict__ outHi, bf16* __restrict__ outLo,
               int M, int N, int K, int gelu_flag)
{
    extern __shared__ __align__(16) char sm[];
    const uint32_t smem_u32 = smem_to_u32(sm);
    const int tid  = threadIdx.x;
    const int wid  = tid >> 5;
    const int lane = tid & 31;
    const int bm = blockIdx.y * 128;
    const int bn = blockIdx.x * 128;
    const int wm = (wid >> 2) * 32;     // warp M offset: 0/32/64/96
    const int wn = (wid & 3) * 32;      // warp N offset: 0/32/64/96

    // global->smem loader coords: one 16B segment per matrix per thread
    const int lrow = tid >> 2;          // 0..127
    const int lseg = tid & 3;           // 16B segment within 64B row

    // ldmatrix lane-relative byte offsets (verified mapping, Round 9):
    const int aRow = (lane & 7) + ((lane >> 3) & 1) * 8;
    const int aCol = (lane >> 4) * 8;
    const uint32_t relA0 = (uint32_t)((wm +  0 + aRow) * SKP * 2 + aCol * 2);
    const uint32_t relA1 = (uint32_t)((wm + 16 + aRow) * SKP * 2 + aCol * 2);
    const int bRow = (lane & 7) + (lane >> 4) * 8;
    const int bCol = ((lane >> 3) & 1) * 8;
    const uint32_t relB0 = (uint32_t)((wn +  0 + bRow) * SKP * 2 + bCol * 2);
    const uint32_t relB1 = (uint32_t)((wn + 16 + bRow) * SKP * 2 + bCol * 2);

    float acc[2][4][4];
#pragma unroll
    for (int i = 0; i < 2; i++)
#pragma unroll
        for (int j = 0; j < 4; j++)
#pragma unroll
            for (int r = 0; r < 4; r++) acc[i][j][r] = 0.0f;

    auto prefetch = [&](int k0, int s) {
        const uint32_t sb = smem_u32 + s * STAGE_BYTES;
        const uint32_t so = (uint32_t)(lrow * (SKP * 2) + lseg * 16);
        const size_t ga = (size_t)(bm + lrow) * K + k0 + lseg * 8;
        const size_t gb = (size_t)(bn + lrow) * K + k0 + lseg * 8;
        CP_ASYNC16(sb + 0 * MAT_BYTES + so, Ahi + ga);
        CP_ASYNC16(sb + 1 * MAT_BYTES + so, Alo + ga);
        CP_ASYNC16(sb + 2 * MAT_BYTES + so, Bhi + gb);
        CP_ASYNC16(sb + 3 * MAT_BYTES + so, Blo + gb);
    };

    const int nchunks = K >> 5;
    prefetch(0, 0);
    CP_COMMIT();

    for (int c = 0; c < nchunks; c++) {
        const int s = c & 1;
        CP_WAIT0();
        __syncthreads();
        if (c + 1 < nchunks) prefetch((c + 1) << 5, s ^ 1);
        CP_COMMIT();

        const uint32_t st = smem_u32 + s * STAGE_BYTES;

#pragma unroll
        for (int kk = 0; kk < 32; kk += 16) {
            const uint32_t kb = st + kk * 2;
            uint32_t ah[8], al[8], bh[8], bl[8];

            LDSM_X4(ah[0], ah[1], ah[2], ah[3], kb + relA0);
            LDSM_X4(ah[4], ah[5], ah[6], ah[7], kb + relA1);
            LDSM_X4(bh[0], bh[1], bh[2], bh[3], kb + 2 * MAT_BYTES + relB0);
            LDSM_X4(bh[4], bh[5], bh[6], bh[7], kb + 2 * MAT_BYTES + relB1);
            LDSM_X4(al[0], al[1], al[2], al[3], kb + MAT_BYTES + relA0);
            LDSM_X4(al[4], al[5], al[6], al[7], kb + MAT_BYTES + relA1);
            LDSM_X4(bl[0], bl[1], bl[2], bl[3], kb + 3 * MAT_BYTES + relB0);
            LDSM_X4(bl[4], bl[5], bl[6], bl[7], kb + 3 * MAT_BYTES + relB1);

            // term-major schedule: no back-to-back acc reuse
#pragma unroll
            for (int mi = 0; mi < 2; mi++)
#pragma unroll
                for (int ni = 0; ni < 4; ni++)
                    mma16816(acc[mi][ni], &ah[mi * 4], &bh[ni * 2]);   // hi*hi
#pragma unroll
            for (int mi = 0; mi < 2; mi++)
#pragma unroll
                for (int ni = 0; ni < 4; ni++)
                    mma16816(acc[mi][ni], &ah[mi * 4], &bl[ni * 2]);   // hi*lo
#pragma unroll
            for (int mi = 0; mi < 2; mi++)
#pragma unroll
                for (int ni = 0; ni < 4; ni++)
                    mma16816(acc[mi][ni], &al[mi * 4], &bh[ni * 2]);   // lo*hi
        }
        __syncthreads();
    }

    // ------------------------------------------------------------------ epilogue
#pragma unroll
    for (int mi = 0; mi < 2; mi++) {
        const int r0 = bm + wm + mi * 16 + (lane >> 2);
#pragma unroll
        for (int ni = 0; ni < 4; ni++) {
            const int c0 = bn + wn + ni * 8 + (lane & 3) * 2;
            const float b0 = bias[c0], b1 = bias[c0 + 1];
            float v0 = acc[mi][ni][0] + b0;
            float v1 = acc[mi][ni][1] + b1;
            float v2 = acc[mi][ni][2] + b0;
            float v3 = acc[mi][ni][3] + b1;
            if (gelu_flag) {
                v0 = gelu_f(v0); v1 = gelu_f(v1);
                v2 = gelu_f(v2); v3 = gelu_f(v3);
            }
            if (outF) {
                *(float2*)(outF + (size_t)r0 * N + c0)       = make_float2(v0, v1);
                *(float2*)(outF + (size_t)(r0 + 8) * N + c0) = make_float2(v2, v3);
            } else {
                const bf16 h0 = __float2bfloat16(v0);
                const bf16 h1 = __float2bfloat16(v1);
                const bf16 h2 = __float2bfloat16(v2);
                const bf16 h3 = __float2bfloat16(v3);
                bf162 hp0; hp0.x = h0; hp0.y = h1;
                bf162 hp1; hp1.x = h2; hp1.y = h3;
                bf162 lp0; lp0.x = __float2bfloat16(v0 - __bfloat162float(h0));
                lp0.y = __float2bfloat16(v1 - __bfloat162float(h1));
                bf162 lp1; lp1.x = __float2bfloat16(v2 - __bfloat162float(h2));
                lp1.y = __float2bfloat16(v3 - __bfloat162float(h3));
                *(bf162*)(outHi + (size_t)r0 * N + c0)       = hp0;
                *(bf162*)(outHi + (size_t)(r0 + 8) * N + c0) = hp1;
                *(bf162*)(outLo + (size_t)r0 * N + c0)       = lp0;
                *(bf162*)(outLo + (size_t)(r0 + 8) * N + c0) = lp1;
            }
        }
    }
}

// ----------------------------------------------------------------------------
// fp32 -> bf16 hi/lo split
// ----------------------------------------------------------------------------
__global__ __launch_bounds__(256)
void split_kernel(const float* __restrict__ in, bf16* __restrict__ hi,
                  bf16* __restrict__ lo, int n)
{
    const int i = (blockIdx.x * 256 + threadIdx.x) * 4;
    if (i >= n) return;
    const float4 v = *(const float4*)(in + i);
    const bf16 h0 = __float2bfloat16(v.x);
    const bf16 h1 = __float2bfloat16(v.y);
    const bf16 h2 = __float2bfloat16(v.z);
    const bf16 h3 = __float2bfloat16(v.w);
    const bf16 l0 = __float2bfloat16(v.x - __bfloat162float(h0));
    const bf16 l1 = __float2bfloat16(v.y - __bfloat162float(h1));
    const bf16 l2 = __float2bfloat16(v.z - __bfloat162float(h2));
    const bf16 l3 = __float2bfloat16(v.w - __bfloat162float(h3));
    bf162 hp0; hp0.x = h0; hp0.y = h1;
    bf162 hp1; hp1.x = h2; hp1.y = h3;
    bf162 lp0; lp0.x = l0; lp0.y = l1;
    bf162 lp1; lp1.x = l2; lp1.y = l3;
    uint2 hv, lv;
    hv.x = *(const uint32_t*)&hp0; hv.y = *(const uint32_t*)&hp1;
    lv.x = *(const uint32_t*)&lp0; lv.y = *(const uint32_t*)&lp1;
    *(uint2*)(hi + i) = hv;
    *(uint2*)(lo + i) = lv;
}

// ----------------------------------------------------------------------------
// Mask normalization (dtype-robust: bool/uint8, int32, or float32 -> uint8)
// ----------------------------------------------------------------------------
__global__ void mask_norm_kernel(const void* __restrict__ mp)
{
    __shared__ int s_nonbin;
    __shared__ int s_offnz;
    const unsigned char* b = (const unsigned char*)mp;
    if (threadIdx.x == 0) { s_nonbin = 0; s_offnz = 0; }
    __syncthreads();

    int local_nonbin = 0, local_offnz = 0;
    for (int i = threadIdx.x; i < MASK_N; i += blockDim.x) {
        unsigned char v = b[i];
        if (v > 1)                  local_nonbin = 1;
        if ((i & 3) != 0 && v != 0) local_offnz = 1;
    }
    if (local_nonbin) atomicOr(&s_nonbin, 1);
    if (local_offnz)  atomicOr(&s_offnz, 1);
    __syncthreads();

    const int nonbin = s_nonbin, offnz = s_offnz;
    if (nonbin) {
        const float* f = (const float*)mp;
        for (int i = threadIdx.x; i < MASK_N; i += blockDim.x)
            g_mask[i] = (f[i] != 0.0f) ? 1 : 0;
    } else if (offnz) {
        for (int i = threadIdx.x; i < MASK_N; i += blockDim.x)
            g_mask[i] = (b[i] != 0) ? 1 : 0;
    } else {
        const int* ip = (const int*)mp;
        for (int i = threadIdx.x; i < MASK_N; i += blockDim.x)
            g_mask[i] = (ip[i] != 0) ? 1 : 0;
    }
}

// ----------------------------------------------------------------------------
// Attention: one warp per (token, head). Writes CTX directly as bf16 hi/lo.
// ----------------------------------------------------------------------------
__global__ __launch_bounds__(256)
void attn_kernel(const float* __restrict__ Q, const float* __restrict__ Kb,
                 const float* __restrict__ Vb,
                 bf16* __restrict__ CXhi, bf16* __restrict__ CXlo)
{
    const int w    = (blockIdx.x * blockDim.x + threadIdx.x) >> 5;
    const int lane = threadIdx.x & 31;
    if (w >= T_TOK * NH) return;
    const int t = w / NH;
    const int h = w % NH;

    const size_t qoff = (size_t)t * HID + h * HD + lane * 2;
    const float2 q = *(const float2*)(Q + qoff);

    float s[NC];
    unsigned allm = 1;
#pragma unroll
    for (int n = 0; n < NC; n++) {
        const float2 kv = *(const float2*)(Kb + ((size_t)t * NC + n) * HID + h * HD + lane * 2);
        float p = q.x * kv.x + q.y * kv.y;
#pragma unroll
        for (int o = 16; o > 0; o >>= 1)
            p += __shfl_xor_sync(0xffffffffu, p, o);
        const unsigned char mn = g_mask[t * NC + n];
        allm &= (mn != 0);
        s[n] = mn ? 1e-10f : p * 0.125f;
    }

    float mx = s[0];
#pragma unroll
    for (int n = 1; n < NC; n++) mx = fmaxf(mx, s[n]);
    float sum = 0.0f;
#pragma unroll
    for (int n = 0; n < NC; n++) { s[n] = expf(s[n] - mx); sum += s[n]; }
    const float inv = 1.0f / sum;

    float2 c = make_float2(0.0f, 0.0f);
#pragma unroll
    for (int n = 0; n < NC; n++) {
        const float2 vv = *(const float2*)(Vb + ((size_t)t * NC + n) * HID + h * HD + lane * 2);
        const float p = s[n] * inv;
        c.x += p * vv.x;
        c.y += p * vv.y;
    }
    if (allm) { c.x = 0.0f; c.y = 0.0f; }

    const bf16 h0 = __float2bfloat16(c.x);
    const bf16 h1 = __float2bfloat16(c.y);
    const bf16 l0 = __float2bfloat16(c.x - __bfloat162float(h0));
    const bf16 l1 = __float2bfloat16(c.y - __bfloat162float(h1));
    bf162 hp; hp.x = h0; hp.y = h1;
    bf162 lp; lp.x = l0; lp.y = l1;
    *(bf162*)(CXhi + qoff) = hp;
    *(bf162*)(CXlo + qoff) = lp;
}

// ----------------------------------------------------------------------------
// Residual + LayerNorm
// ----------------------------------------------------------------------------
__global__ __launch_bounds__(256)
void ln_kernel(const float* __restrict__ Y, const float* __restrict__ X,
               const float* __restrict__ gamma, const float* __restrict__ beta,
               float* __restrict__ O)
{
    const int t   = blockIdx.x;
    const int tid = threadIdx.x;
    const float* yp = Y + (size_t)t * HID;
    const float* xp = X + (size_t)t * HID;

    float v[3];
    float sum = 0.0f, sq = 0.0f;
#pragma unroll
    for (int i = 0; i < 3; i++) {
        const int idx = tid + i * 256;
        v[i] = yp[idx] + xp[idx];
        sum += v[i];
        sq  += v[i] * v[i];
    }

    const int lane = tid & 31, wid = tid >> 5;
#pragma unroll
    for (int o = 16; o > 0; o >>= 1) {
        sum += __shfl_xor_sync(0xffffffffu, sum, o);
        sq  += __shfl_xor_sync(0xffffffffu, sq,  o);
    }
    __shared__ float rs[8], rq[8];
    if (lane == 0) { rs[wid] = sum; rq[wid] = sq; }
    __syncthreads();
    sum = 0.0f; sq = 0.0f;
#pragma unroll
    for (int i = 0; i < 8; i++) { sum += rs[i]; sq += rq[i]; }

    const float mean = sum * (1.0f / HID);
    const float var  = sq * (1.0f / HID) - mean * mean;
    const float inv  = rsqrtf(var + 1e-12f);

    float* op = O + (size_t)t * HID;
#pragma unroll
    for (int i = 0; i < 3; i++) {
        const int idx = tid + i * 256;
        op[idx] = (v[i] - mean) * inv * gamma[idx] + beta[idx];
    }
}

// ----------------------------------------------------------------------------
// kernel_launch
// ----------------------------------------------------------------------------
extern "C" void kernel_launch(void* const* d_in, const int* in_sizes, int n_in,
                              void* d_out, int out_size)
{
    const float* X    = (const float*)d_in[0];
    const float* Cand = (const float*)d_in[1];
    const void*  Mask = d_in[2];
    const float* Wq   = (const float*)d_in[3];
    const float* bq   = (const float*)d_in[4];
    const float* Wk   = (const float*)d_in[5];
    const float* bk   = (const float*)d_in[6];
    const float* Wv   = (const float*)d_in[7];
    const float* bv   = (const float*)d_in[8];
    const float* Wt   = (const float*)d_in[9];
    const float* bt   = (const float*)d_in[10];
    const float* Wc   = (const float*)d_in[11];
    const float* bc   = (const float*)d_in[12];
    const float* gam  = (const float*)d_in[13];
    const float* bet  = (const float*)d_in[14];
    float* out = (float*)d_out;

    void *pQ, *pK, *pV, *pY;
    void *pXhi, *pXlo, *pChi, *pClo;
    void *pWqhi, *pWqlo, *pWkhi, *pWklo, *pWvhi, *pWvlo;
    void *pWthi, *pWtlo, *pWchi, *pWclo;
    void *pCXhi, *pCXlo, *pHhi, *pHlo;
    cudaGetSymbolAddress(&pQ, g_Q);     cudaGetSymbolAddress(&pK, g_K);
    cudaGetSymbolAddress(&pV, g_V);     cudaGetSymbolAddress(&pY, g_Y);
    cudaGetSymbolAddress(&pXhi, g_Xhi); cudaGetSymbolAddress(&pXlo, g_Xlo);
    cudaGetSymbolAddress(&pChi, g_Chi); cudaGetSymbolAddress(&pClo, g_Clo);
    cudaGetSymbolAddress(&pWqhi, g_Wqhi); cudaGetSymbolAddress(&pWqlo, g_Wqlo);
    cudaGetSymbolAddress(&pWkhi, g_Wkhi); cudaGetSymbolAddress(&pWklo, g_Wklo);
    cudaGetSymbolAddress(&pWvhi, g_Wvhi); cudaGetSymbolAddress(&pWvlo, g_Wvlo);
    cudaGetSymbolAddress(&pWthi, g_Wthi); cudaGetSymbolAddress(&pWtlo, g_Wtlo);
    cudaGetSymbolAddress(&pWchi, g_Wchi); cudaGetSymbolAddress(&pWclo, g_Wclo);
    cudaGetSymbolAddress(&pCXhi, g_CXhi); cudaGetSymbolAddress(&pCXlo, g_CXlo);
    cudaGetSymbolAddress(&pHhi, g_Hhi);   cudaGetSymbolAddress(&pHlo, g_Hlo);

    cudaFuncSetAttribute(gemm_bf16split,
                         cudaFuncAttributeMaxDynamicSharedMemorySize,
                         GEMM_SMEM_TOTAL);

    // 0. mask normalization
    mask_norm_kernel<<<1, 1024>>>(Mask);

    // 1. fp32 -> bf16 hi/lo splits of all GEMM inputs
    split_kernel<<<(T_TOK * HID) / 1024, 256>>>(X,    (bf16*)pXhi, (bf16*)pXlo, T_TOK * HID);
    split_kernel<<<(CAND_M * HID) / 1024, 256>>>(Cand,(bf16*)pChi, (bf16*)pClo, CAND_M * HID);
    split_kernel<<<(HID * HID) / 1024, 256>>>(Wq,     (bf16*)pWqhi,(bf16*)pWqlo,HID * HID);
    split_kernel<<<(HID * HID) / 1024, 256>>>(Wk,     (bf16*)pWkhi,(bf16*)pWklo,HID * HID);
    split_kernel<<<(HID * HID) / 1024, 256>>>(Wv,     (bf16*)pWvhi,(bf16*)pWvlo,HID * HID);
    split_kernel<<<(FF * HID) / 1024, 256>>>(Wt,      (bf16*)pWthi,(bf16*)pWtlo,FF * HID);
    split_kernel<<<(HID * FF) / 1024, 256>>>(Wc,      (bf16*)pWchi,(bf16*)pWclo,HID * FF);

    // 2. Q = X @ Wq^T + bq   (fp32 out)
    {
        dim3 g(HID / 128, T_TOK / 128);
        gemm_bf16split<<<g, 512, GEMM_SMEM_TOTAL>>>(
            (const bf16*)pXhi, (const bf16*)pXlo,
            (const bf16*)pWqhi,(const bf16*)pWqlo, bq,
            (float*)pQ, nullptr, nullptr, T_TOK, HID, HID, 0);
    }
    // 3/4. K,V = Cand @ {Wk,Wv}^T + {bk,bv}   (fp32 out)
    {
        dim3 g(HID / 128, CAND_M / 128);
        gemm_bf16split<<<g, 512, GEMM_SMEM_TOTAL>>>(
            (const bf16*)pChi, (const bf16*)pClo,
            (const bf16*)pWkhi,(const bf16*)pWklo, bk,
            (float*)pK, nullptr, nullptr, CAND_M, HID, HID, 0);
        gemm_bf16split<<<g, 512, GEMM_SMEM_TOTAL>>>(
            (const bf16*)pChi, (const bf16*)pClo,
            (const bf16*)pWvhi,(const bf16*)pWvlo, bv,
            (float*)pV, nullptr, nullptr, CAND_M, HID, HID, 0);
    }
    // 5. attention -> CTX (bf16 hi/lo)
    attn_kernel<<<(T_TOK * NH) / 8, 256>>>((const float*)pQ, (const float*)pK,
                                           (const float*)pV,
                                           (bf16*)pCXhi, (bf16*)pCXlo);
    // 6. H = gelu(CTX @ Wt^T + bt)   (bf16 hi/lo out)
    {
        dim3 g(FF / 128, T_TOK / 128);
        gemm_bf16split<<<g, 512, GEMM_SMEM_TOTAL>>>(
            (const bf16*)pCXhi,(const bf16*)pCXlo,
            (const bf16*)pWthi,(const bf16*)pWtlo, bt,
            nullptr, (bf16*)pHhi, (bf16*)pHlo, T_TOK, FF, HID, 1);
    }
    // 7. Y = H @ Wc^T + bc   (fp32 out)
    {
        dim3 g(HID / 128, T_TOK / 128);
        gemm_bf16split<<<g, 512, GEMM_SMEM_TOTAL>>>(
            (const bf16*)pHhi, (const bf16*)pHlo,
            (const bf16*)pWchi,(const bf16*)pWclo, bc,
            (float*)pY, nullptr, nullptr, T_TOK, HID, FF, 0);
    }
    // 8. out = LayerNorm(Y + X)
    ln_kernel<<<T_TOK, 256>>>((const float*)pY, X, gam, bet, out);
}